// round 11
// baseline (speedup 1.0000x reference)
#include <cuda_runtime.h>
#include <cuda_bf16.h>
#include <math.h>

#define Bv 8
#define Tv 2048
#define Cv 1024
#define HSv 64
#define Mv (Bv*Tv)
#define QT 128
#define SLOTS 8

typedef unsigned long long u64;
typedef unsigned int u32;

// ---------- cp.async ----------
__device__ __forceinline__ void cp16(void* dst_smem, const void* src){
    unsigned d = (unsigned)__cvta_generic_to_shared(dst_smem);
    asm volatile("cp.async.cg.shared.global [%0], [%1], 16;" :: "r"(d), "l"(src));
}
#define CP_COMMIT() asm volatile("cp.async.commit_group;")
#define CP_WAIT0()  asm volatile("cp.async.wait_group 0;")
#define CP_WAIT1()  asm volatile("cp.async.wait_group 1;")
#define CP_WAIT2()  asm volatile("cp.async.wait_group 2;")
#define CP_WAIT3()  asm volatile("cp.async.wait_group 3;")

// ---------- mma.sync helpers ----------
__device__ __forceinline__ u32 smem_u32(const void* p){
    return (u32)__cvta_generic_to_shared(p);
}
__device__ __forceinline__ void ldsm_x4(u32 &r0,u32 &r1,u32 &r2,u32 &r3, u32 addr){
    asm volatile("ldmatrix.sync.aligned.m8n8.x4.shared.b16 {%0,%1,%2,%3}, [%4];"
        : "=r"(r0),"=r"(r1),"=r"(r2),"=r"(r3) : "r"(addr));
}
__device__ __forceinline__ void ldsm_x2(u32 &r0,u32 &r1, u32 addr){
    asm volatile("ldmatrix.sync.aligned.m8n8.x2.shared.b16 {%0,%1}, [%2];"
        : "=r"(r0),"=r"(r1) : "r"(addr));
}
__device__ __forceinline__ void ldsm_x2t(u32 &r0,u32 &r1, u32 addr){
    asm volatile("ldmatrix.sync.aligned.m8n8.x2.trans.shared.b16 {%0,%1}, [%2];"
        : "=r"(r0),"=r"(r1) : "r"(addr));
}
__device__ __forceinline__ void mma16816(float* d, const u32* a, const u32* b){
    asm volatile("mma.sync.aligned.m16n8k16.row.col.f32.bf16.bf16.f32 "
        "{%0,%1,%2,%3}, {%4,%5,%6,%7}, {%8,%9}, {%0,%1,%2,%3};"
        : "+f"(d[0]),"+f"(d[1]),"+f"(d[2]),"+f"(d[3])
        : "r"(a[0]),"r"(a[1]),"r"(a[2]),"r"(a[3]), "r"(b[0]),"r"(b[1]));
}

__device__ __forceinline__ void split_pair(float x, float y, u32 &h, u32 &lo){
    __nv_bfloat162 hh = __floats2bfloat162_rn(x, y);
    float2 fo = __bfloat1622float2(hh);
    __nv_bfloat162 ll = __floats2bfloat162_rn(x - fo.x, y - fo.y);
    h  = *(u32*)&hh;
    lo = *(u32*)&ll;
}

// ---------- scratch ----------
__device__ __nv_bfloat16 g_abuf[6*(size_t)Mv*HSv];
__device__ float g_pacc[(size_t)SLOTS*Mv*HSv];
__device__ float g_pm[SLOTS*Mv];
__device__ float g_pl[SLOTS*Mv];
__device__ __nv_bfloat16 g_wt[3*2*64*1024];   // [z][hi/lo][n][k]
__device__ int g_cnt[Bv*16];                  // per-(b,qb) completion counters

// =====================================================================
// Kernel 0: transpose + bf16-split weights
// =====================================================================
__global__ __launch_bounds__(256) void prep_wt(
    const float* __restrict__ Wq, const float* __restrict__ Wk,
    const float* __restrict__ Wv)
{
    int id = blockIdx.x*256 + threadIdx.x;
    int z = id >> 16; int rem = id & 65535;
    int n = rem >> 10; int k = rem & 1023;
    const float* W = (z==0) ? Wq : (z==1) ? Wk : Wv;
    float w = W[k*64 + n];
    __nv_bfloat16 h = __float2bfloat16(w);
    float r = w - __bfloat162float(h);
    g_wt[(size_t)(z*2+0)*65536 + n*1024 + k] = h;
    g_wt[(size_t)(z*2+1)*65536 + n*1024 + k] = __float2bfloat16(r);
}

// =====================================================================
// Kernel 1: HMMA split-bf16 projection, 512 threads (16 warps, 4/SMSP).
// Warp tile 16x32; B fragments via paired ldmatrix.x4; pipelined A cvt.
// =====================================================================
#define KCH 64
#define NCHUNK (Cv/KCH)
#define A_HI 0
#define A_LO 36864
#define B_HI 73728
#define B_LO 110592
#define PROJ_SMEM 147456

__device__ __forceinline__ void cvt_split4(float4 a, uint2 &hi, uint2 &lo){
    __nv_bfloat162 h01 = __floats2bfloat162_rn(a.x, a.y);
    __nv_bfloat162 h23 = __floats2bfloat162_rn(a.z, a.w);
    float2 f01 = __bfloat1622float2(h01);
    float2 f23 = __bfloat1622float2(h23);
    __nv_bfloat162 l01 = __floats2bfloat162_rn(a.x - f01.x, a.y - f01.y);
    __nv_bfloat162 l23 = __floats2bfloat162_rn(a.z - f23.x, a.w - f23.y);
    hi.x = *(u32*)&h01; hi.y = *(u32*)&h23;
    lo.x = *(u32*)&l01; lo.y = *(u32*)&l23;
}

__global__ __launch_bounds__(512) void proj_mma(
    const float* __restrict__ qv, const float* __restrict__ kvec,
    const float* __restrict__ vv)
{
    extern __shared__ __align__(128) char smc[];
    const int t   = threadIdx.x;
    const int wid = t >> 5;
    const int l   = t & 31;
    const int z   = blockIdx.y;
    const int m0  = blockIdx.x * 128;
    const float* A = (z==0) ? qv : (z==1) ? kvec : vv;

    const u32 sbase = smem_u32(smc);
    const int wm = wid >> 1;        // 0..7 (16-row groups)
    const int wn = wid & 1;         // 0..1 (32-col groups)

    // A ldmatrix.x4 lane geometry (16x16 tile)
    const int arow  = (l & 15);
    const int acol8 = (l >> 4) * 8;
    // B paired-x4 lane geometry: two 8-row n-groups x two k-halves in one x4
    const int bprow = (l & 7) + ((l >> 3) & 1) * 8;   // row within 16-row pair
    const int bk8   = (l >> 4) * 8;                   // k half

    auto loadB = [&](int it2){
        int slot = it2 & 3; int k0 = it2 * KCH;
        #pragma unroll
        for (int i = 0; i < 2; i++){
            int idx = t + i*512;              // 0..1023
            int term = idx >> 9;
            int rem = idx & 511;
            int n = rem >> 3, c = rem & 7;
            cp16(smc + (term ? B_LO : B_HI) + slot*9216 + n*144 + c*16,
                 g_wt + (size_t)(z*2+term)*65536 + n*1024 + k0 + c*8);
        }
    };

    float4 aPre[4];
    auto loadA = [&](int it2){
        int k0 = it2 * KCH;
        #pragma unroll
        for (int i = 0; i < 4; i++){
            int idx = t + i*512; int r = idx >> 4, c4 = idx & 15;
            aPre[i] = *(const float4*)(A + (size_t)(m0 + r)*Cv + k0 + c4*4);
        }
    };

    auto stsA = [&](int buf){
        #pragma unroll
        for (int i = 0; i < 4; i++){
            int idx = t + i*512; int r = idx >> 4, c4 = idx & 15;
            uint2 hi, lo; cvt_split4(aPre[i], hi, lo);
            *(uint2*)(smc + A_HI + buf*18432 + r*144 + c4*8) = hi;
            *(uint2*)(smc + A_LO + buf*18432 + r*144 + c4*8) = lo;
        }
    };

    // prologue
    loadA(0);
    loadB(0); CP_COMMIT();
    loadB(1); CP_COMMIT();
    stsA(0);
    loadA(1);
    __syncthreads();

    float D[4][4];
    #pragma unroll
    for (int nc = 0; nc < 4; nc++)
        #pragma unroll
        for (int e = 0; e < 4; e++) D[nc][e] = 0.f;

    #pragma unroll 1
    for (int it = 0; it < NCHUNK; it++){
        if (it < NCHUNK-1) { CP_WAIT1(); } else { CP_WAIT0(); }   // B(it) resident
        const int buf = it & 1;
        const int slot = it & 3;

        if (it + 2 < NCHUNK){ loadB(it + 2); CP_COMMIT(); }

        const u32 aHiB = sbase + A_HI + buf*18432;
        const u32 aLoB = sbase + A_LO + buf*18432;
        const u32 bHiB = sbase + B_HI + slot*9216;
        const u32 bLoB = sbase + B_LO + slot*9216;

        #pragma unroll
        for (int ks = 0; ks < 4; ks++){
            u32 AH[4], AL[4], BH[4][2], BL[4][2];
            {
                u32 ao = (u32)((wm*16 + arow)*144 + (ks*16 + acol8)*2);
                ldsm_x4(AH[0], AH[1], AH[2], AH[3], aHiB + ao);
                ldsm_x4(AL[0], AL[1], AL[2], AL[3], aLoB + ao);
            }
            #pragma unroll
            for (int pr = 0; pr < 2; pr++){
                u32 bo = (u32)((wn*32 + pr*16 + bprow)*144 + (ks*16 + bk8)*2);
                u32 r0, r1, r2, r3;
                ldsm_x4(r0, r1, r2, r3, bHiB + bo);
                BH[pr*2+0][0] = r0; BH[pr*2+0][1] = r2;
                BH[pr*2+1][0] = r1; BH[pr*2+1][1] = r3;
                ldsm_x4(r0, r1, r2, r3, bLoB + bo);
                BL[pr*2+0][0] = r0; BL[pr*2+0][1] = r2;
                BL[pr*2+1][0] = r1; BL[pr*2+1][1] = r3;
            }
            #pragma unroll
            for (int nc = 0; nc < 4; nc++){
                mma16816(D[nc], AH, BH[nc]);
                mma16816(D[nc], AH, BL[nc]);
                mma16816(D[nc], AL, BH[nc]);
            }
        }

        // hidden under the tensor phase: convert+store A(it+1), prefetch A(it+2)
        if (it + 1 < NCHUNK){
            stsA((it + 1) & 1);
            if (it + 2 < NCHUNK) loadA(it + 2);
        }
        __syncthreads();
    }

    const float sc = (z == 0) ? 0.125f : 1.0f;
    __nv_bfloat16* ghi = g_abuf + (size_t)(z*2+0)*Mv*HSv;
    __nv_bfloat16* glo = g_abuf + (size_t)(z*2+1)*Mv*HSv;
    {
        int row = m0 + wm*16 + (l >> 2);
        #pragma unroll
        for (int nc = 0; nc < 4; nc++){
            int col = wn*32 + nc*8 + (l & 3)*2;
            u32 h0, l0, h1, l1;
            split_pair(D[nc][0]*sc, D[nc][1]*sc, h0, l0);
            split_pair(D[nc][2]*sc, D[nc][3]*sc, h1, l1);
            *(u32*)(ghi + (size_t)row*HSv + col)     = h0;
            *(u32*)(glo + (size_t)row*HSv + col)     = l0;
            *(u32*)(ghi + (size_t)(row+8)*HSv + col) = h1;
            *(u32*)(glo + (size_t)(row+8)*HSv + col) = l1;
        }
    }
}

// =====================================================================
// Kernel 2: HMMA attention + fused last-CTA merge.
// =====================================================================
#define AQH 0
#define AQL 18432
#define SUBOFF(s2) (36864 + (s2)*73728)      // KH +0, KL +18432, VH +36864, VL +55296
#define AMSK 184320
#define ATTN_SMEM (184320 + 1024)

__global__ __launch_bounds__(256, 1) void attn_mma(const int* __restrict__ mask,
                                                   float* __restrict__ out)
{
    extern __shared__ __align__(128) char smc[];
    __shared__ int s_old;
    const u32 sbase = smem_u32(smc);
    int* Msk = (int*)(smc + AMSK);           // [2][128]

    // decode (qb, s): cum(qb) = floor((qb+1)^2/4)
    int x = blockIdx.x;
    int qb = (int)(2.f*sqrtf((float)(x+1))) - 1;
    if (qb < 0) qb = 0; if (qb > 15) qb = 15;
    while (qb < 15 && ((qb+2)*(qb+2))/4 <= x) qb++;
    while (qb > 0 && ((qb+1)*(qb+1))/4 > x) qb--;
    const int s = x - ((qb+1)*(qb+1))/4;

    const int b  = blockIdx.y;
    const int t  = threadIdx.x;
    const int w  = t >> 5;
    const int l  = t & 31;
    const int bT = b*Tv;
    const int row0 = qb*QT;
    const int ks0 = s*256;
    const int nsub = (min(256, (qb+1)*128 - ks0)) >> 7;   // 1 or 2

    auto load_arr = [&](int aa, int dst_off, int src_row0){
        const __nv_bfloat16* src = g_abuf + (size_t)aa*Mv*HSv + (size_t)(bT + src_row0)*HSv;
        #pragma unroll
        for (int i = 0; i < 4; i++){
            int idx = t + i*256; int r = idx >> 3, c = idx & 7;
            cp16(smc + dst_off + r*144 + c*16, src + r*64 + c*8);
        }
    };
    load_arr(2, SUBOFF(0) + 0,     ks0);
    load_arr(3, SUBOFF(0) + 18432, ks0);
    load_arr(0, AQH, row0);
    load_arr(1, AQL, row0);
    if (t < 32) cp16(&Msk[t*4], mask + bT + ks0 + t*4);
    CP_COMMIT();
    load_arr(4, SUBOFF(0) + 36864, ks0);
    load_arr(5, SUBOFF(0) + 55296, ks0);
    CP_COMMIT();
    if (nsub == 2){
        load_arr(2, SUBOFF(1) + 0,     ks0 + 128);
        load_arr(3, SUBOFF(1) + 18432, ks0 + 128);
        if (t < 32) cp16(&Msk[128 + t*4], mask + bT + ks0 + 128 + t*4);
    }
    CP_COMMIT();
    if (nsub == 2){
        load_arr(4, SUBOFF(1) + 36864, ks0 + 128);
        load_arr(5, SUBOFF(1) + 55296, ks0 + 128);
    }
    CP_COMMIT();

    const int arow  = (l & 15);
    const int acol8 = (l >> 4) * 8;
    const int brow  = (l & 7);
    const int bk8   = ((l >> 3) & 1) * 8;
    const int vofs  = (l & 15) * 144;

    CP_WAIT3();
    __syncthreads();

    u32 QH4[4][4], QL4[4][4];
    #pragma unroll
    for (int ks = 0; ks < 4; ks++){
        u32 ao = (u32)((w*16 + arow)*144 + (ks*16 + acol8)*2);
        ldsm_x4(QH4[ks][0], QH4[ks][1], QH4[ks][2], QH4[ks][3], sbase + AQH + ao);
        ldsm_x4(QL4[ks][0], QL4[ks][1], QL4[ks][2], QL4[ks][3], sbase + AQL + ao);
    }

    const int g  = l >> 2;
    const int qx = l & 3;
    const int r0g = row0 + w*16 + g;
    const int r1g = r0g + 8;

    float mraw0 = -INFINITY, mraw1 = -INFINITY;
    float mC0 = -1e30f, mC1 = -1e30f;
    float l0 = 0.f, l1 = 0.f;
    float O[8][4];
    #pragma unroll
    for (int nb = 0; nb < 8; nb++)
        #pragma unroll
        for (int e = 0; e < 4; e++) O[nb][e] = 0.f;

    #pragma unroll 1
    for (int sub = 0; sub < nsub; sub++){
        if (sub == 1){ CP_WAIT1(); __syncthreads(); }
        const u32 kbase = sbase + SUBOFF(sub);
        const int msub = sub*128;
        const int ksub = ks0 + sub*128;

        float S[16][4];
        #pragma unroll
        for (int nt = 0; nt < 16; nt++)
            #pragma unroll
            for (int e = 0; e < 4; e++) S[nt][e] = 0.f;

        #pragma unroll
        for (int ks = 0; ks < 4; ks++){
            #pragma unroll
            for (int nt = 0; nt < 16; nt++){
                u32 bo = (u32)((nt*8 + brow)*144 + (ks*16 + bk8)*2);
                u32 BH0, BH1, BL0, BL1;
                ldsm_x2(BH0, BH1, kbase + bo);
                ldsm_x2(BL0, BL1, kbase + 18432 + bo);
                u32 BH[2] = {BH0, BH1}, BL[2] = {BL0, BL1};
                mma16816(S[nt], QH4[ks], BH);
                mma16816(S[nt], QH4[ks], BL);
                mma16816(S[nt], QL4[ks], BH);
            }
        }

        float tm0 = -INFINITY, tm1 = -INFINITY;
        #pragma unroll
        for (int nt = 0; nt < 16; nt++){
            int kb = ksub + nt*8 + qx*2;
            bool va = (kb   <= r0g) && Msk[msub + nt*8 + qx*2];
            bool vb = (kb+1 <= r0g) && Msk[msub + nt*8 + qx*2 + 1];
            bool vc = (kb   <= r1g) && Msk[msub + nt*8 + qx*2];
            bool vd = (kb+1 <= r1g) && Msk[msub + nt*8 + qx*2 + 1];
            S[nt][0] = va ? S[nt][0] : -INFINITY;
            S[nt][1] = vb ? S[nt][1] : -INFINITY;
            S[nt][2] = vc ? S[nt][2] : -INFINITY;
            S[nt][3] = vd ? S[nt][3] : -INFINITY;
            tm0 = fmaxf(tm0, fmaxf(S[nt][0], S[nt][1]));
            tm1 = fmaxf(tm1, fmaxf(S[nt][2], S[nt][3]));
        }
        tm0 = fmaxf(tm0, __shfl_xor_sync(0xFFFFFFFFu, tm0, 1));
        tm0 = fmaxf(tm0, __shfl_xor_sync(0xFFFFFFFFu, tm0, 2));
        tm1 = fmaxf(tm1, __shfl_xor_sync(0xFFFFFFFFu, tm1, 1));
        tm1 = fmaxf(tm1, __shfl_xor_sync(0xFFFFFFFFu, tm1, 2));

        mraw0 = fmaxf(mraw0, tm0);
        mraw1 = fmaxf(mraw1, tm1);
        float mC0n = fmaxf(mraw0, -1e30f);
        float mC1n = fmaxf(mraw1, -1e30f);
        float sc0 = __expf(mC0 - mC0n);
        float sc1 = __expf(mC1 - mC1n);
        mC0 = mC0n; mC1 = mC1n;

        float ps0 = 0.f, ps1 = 0.f;
        #pragma unroll
        for (int nt = 0; nt < 16; nt++){
            S[nt][0] = __expf(S[nt][0] - mC0);
            S[nt][1] = __expf(S[nt][1] - mC0);
            S[nt][2] = __expf(S[nt][2] - mC1);
            S[nt][3] = __expf(S[nt][3] - mC1);
            ps0 += S[nt][0] + S[nt][1];
            ps1 += S[nt][2] + S[nt][3];
        }
        ps0 += __shfl_xor_sync(0xFFFFFFFFu, ps0, 1);
        ps0 += __shfl_xor_sync(0xFFFFFFFFu, ps0, 2);
        ps1 += __shfl_xor_sync(0xFFFFFFFFu, ps1, 1);
        ps1 += __shfl_xor_sync(0xFFFFFFFFu, ps1, 2);
        l0 = l0*sc0 + ps0;
        l1 = l1*sc1 + ps1;

        #pragma unroll
        for (int nb = 0; nb < 8; nb++){
            O[nb][0] *= sc0; O[nb][1] *= sc0;
            O[nb][2] *= sc1; O[nb][3] *= sc1;
        }

        if (sub == 0){ CP_WAIT2(); } else { CP_WAIT0(); }
        __syncthreads();
        const u32 vbase = kbase + 36864;

        #pragma unroll
        for (int ks = 0; ks < 8; ks++){
            u32 Ph[4], Pl[4];
            split_pair(S[2*ks][0],   S[2*ks][1],   Ph[0], Pl[0]);
            split_pair(S[2*ks][2],   S[2*ks][3],   Ph[1], Pl[1]);
            split_pair(S[2*ks+1][0], S[2*ks+1][1], Ph[2], Pl[2]);
            split_pair(S[2*ks+1][2], S[2*ks+1][3], Ph[3], Pl[3]);
            #pragma unroll
            for (int nb = 0; nb < 8; nb++){
                u32 bo = (u32)(ks*16*144 + vofs + nb*16);
                u32 BH0, BH1, BL0, BL1;
                ldsm_x2t(BH0, BH1, vbase + bo);
                ldsm_x2t(BL0, BL1, vbase + 18432 + bo);
                u32 BH[2] = {BH0, BH1}, BL[2] = {BL0, BL1};
                mma16816(O[nb], Ph, BH);
                mma16816(O[nb], Ph, BL);
                mma16816(O[nb], Pl, BH);
            }
        }
    }

    // ---- write unnormalized partials ----
    if (qx == 0){
        g_pm[s*Mv + bT + r0g] = mraw0;  g_pl[s*Mv + bT + r0g] = l0;
        g_pm[s*Mv + bT + r1g] = mraw1;  g_pl[s*Mv + bT + r1g] = l1;
    }
    #pragma unroll
    for (int nb = 0; nb < 8; nb++){
        int col = nb*8 + qx*2;
        *(float2*)(g_pacc + ((size_t)s*Mv + bT + r0g)*HSv + col) = make_float2(O[nb][0], O[nb][1]);
        *(float2*)(g_pacc + ((size_t)s*Mv + bT + r1g)*HSv + col) = make_float2(O[nb][2], O[nb][3]);
    }

    // ---- last CTA for this (b, qb) merges all partials into out ----
    const int ns_total = (qb + 2) >> 1;
    __threadfence();
    __syncthreads();
    if (t == 0) s_old = atomicAdd(&g_cnt[b*16 + qb], 1);
    __syncthreads();
    if (s_old == ns_total - 1){
        __threadfence();
        #pragma unroll 1
        for (int idx = t; idx < 128*16; idx += 256){
            int grow = bT + row0 + (idx >> 4);
            int c4 = idx & 15;
            float M = -INFINITY;
            for (int s2 = 0; s2 < ns_total; s2++)
                M = fmaxf(M, g_pm[s2*Mv + grow]);
            float4 o = make_float4(0.f, 0.f, 0.f, 0.f);
            if (M > -INFINITY){
                float denom = 0.f;
                for (int s2 = 0; s2 < ns_total; s2++){
                    float wgt = __expf(g_pm[s2*Mv + grow] - M);
                    denom += g_pl[s2*Mv + grow] * wgt;
                    float4 a = ((const float4*)g_pacc)[((size_t)s2*Mv + grow)*16 + c4];
                    o.x += a.x*wgt; o.y += a.y*wgt;
                    o.z += a.z*wgt; o.w += a.w*wgt;
                }
                float inv = (denom > 0.f) ? 1.f/denom : 0.f;
                o.x *= inv; o.y *= inv; o.z *= inv; o.w *= inv;
            }
            ((float4*)out)[(size_t)grow*16 + c4] = o;
        }
        __syncthreads();
        if (t == 0) g_cnt[b*16 + qb] = 0;    // reset for next graph replay
    }
}

// =====================================================================
extern "C" void kernel_launch(void* const* d_in, const int* in_sizes, int n_in,
                              void* d_out, int out_size)
{
    const float* q_vec = (const float*)d_in[0];
    const float* k_vec = (const float*)d_in[1];
    const float* v_vec = (const float*)d_in[2];
    const int*   mask  = (const int*)  d_in[3];
    const float* Wq    = (const float*)d_in[4];
    const float* Wk    = (const float*)d_in[5];
    const float* Wv    = (const float*)d_in[6];
    float* out = (float*)d_out;

    cudaFuncSetAttribute(proj_mma,
        cudaFuncAttributeMaxDynamicSharedMemorySize, PROJ_SMEM);
    cudaFuncSetAttribute(attn_mma,
        cudaFuncAttributeMaxDynamicSharedMemorySize, ATTN_SMEM);

    prep_wt<<<768, 256>>>(Wq, Wk, Wv);
    proj_mma<<<dim3(Mv/128, 3), 512, PROJ_SMEM>>>(q_vec, k_vec, v_vec);
    attn_mma<<<dim3(72, Bv), 256, ATTN_SMEM>>>(mask, out);
}

// round 12
// speedup vs baseline: 1.0378x; 1.0378x over previous
#include <cuda_runtime.h>
#include <cuda_bf16.h>
#include <math.h>

#define Bv 8
#define Tv 2048
#define Cv 1024
#define HSv 64
#define Mv (Bv*Tv)
#define QT 128
#define SLOTS 8

typedef unsigned long long u64;
typedef unsigned int u32;

// ---------- cp.async ----------
__device__ __forceinline__ void cp16(void* dst_smem, const void* src){
    unsigned d = (unsigned)__cvta_generic_to_shared(dst_smem);
    asm volatile("cp.async.cg.shared.global [%0], [%1], 16;" :: "r"(d), "l"(src));
}
#define CP_COMMIT() asm volatile("cp.async.commit_group;")
#define CP_WAIT0()  asm volatile("cp.async.wait_group 0;")
#define CP_WAIT1()  asm volatile("cp.async.wait_group 1;")
#define CP_WAIT2()  asm volatile("cp.async.wait_group 2;")
#define CP_WAIT3()  asm volatile("cp.async.wait_group 3;")

// ---------- mma.sync helpers ----------
__device__ __forceinline__ u32 smem_u32(const void* p){
    return (u32)__cvta_generic_to_shared(p);
}
__device__ __forceinline__ void ldsm_x4(u32 &r0,u32 &r1,u32 &r2,u32 &r3, u32 addr){
    asm volatile("ldmatrix.sync.aligned.m8n8.x4.shared.b16 {%0,%1,%2,%3}, [%4];"
        : "=r"(r0),"=r"(r1),"=r"(r2),"=r"(r3) : "r"(addr));
}
__device__ __forceinline__ void ldsm_x2(u32 &r0,u32 &r1, u32 addr){
    asm volatile("ldmatrix.sync.aligned.m8n8.x2.shared.b16 {%0,%1}, [%2];"
        : "=r"(r0),"=r"(r1) : "r"(addr));
}
__device__ __forceinline__ void ldsm_x2t(u32 &r0,u32 &r1, u32 addr){
    asm volatile("ldmatrix.sync.aligned.m8n8.x2.trans.shared.b16 {%0,%1}, [%2];"
        : "=r"(r0),"=r"(r1) : "r"(addr));
}
__device__ __forceinline__ void mma16816(float* d, const u32* a, const u32* b){
    asm volatile("mma.sync.aligned.m16n8k16.row.col.f32.bf16.bf16.f32 "
        "{%0,%1,%2,%3}, {%4,%5,%6,%7}, {%8,%9}, {%0,%1,%2,%3};"
        : "+f"(d[0]),"+f"(d[1]),"+f"(d[2]),"+f"(d[3])
        : "r"(a[0]),"r"(a[1]),"r"(a[2]),"r"(a[3]), "r"(b[0]),"r"(b[1]));
}

__device__ __forceinline__ void split_pair(float x, float y, u32 &h, u32 &lo){
    __nv_bfloat162 hh = __floats2bfloat162_rn(x, y);
    float2 fo = __bfloat1622float2(hh);
    __nv_bfloat162 ll = __floats2bfloat162_rn(x - fo.x, y - fo.y);
    h  = *(u32*)&hh;
    lo = *(u32*)&ll;
}

// ---------- scratch ----------
__device__ __nv_bfloat16 g_abuf[6*(size_t)Mv*HSv];
__device__ float g_pacc[(size_t)SLOTS*Mv*HSv];
__device__ float g_pm[SLOTS*Mv];
__device__ float g_pl[SLOTS*Mv];
__device__ __nv_bfloat16 g_wt[3*2*64*1024];   // [z][hi/lo][n][k]
__device__ int g_cnt[Bv*16];                  // per-(b,qb) completion counters

// =====================================================================
// Kernel 0: transpose + bf16-split weights, coalesced both sides.
// 48 blocks: z (3) x k-block (16). Tile 64k x 64n through padded smem.
// =====================================================================
__global__ __launch_bounds__(256) void prep_wt(
    const float* __restrict__ Wq, const float* __restrict__ Wk,
    const float* __restrict__ Wv)
{
    __shared__ float tile[64*65];
    const int z  = blockIdx.x / 16;
    const int k0 = (blockIdx.x % 16) * 64;
    const int t  = threadIdx.x;
    const float* W = (z==0) ? Wq : (z==1) ? Wk : Wv;

    // coalesced read: adjacent threads -> adjacent n
    #pragma unroll
    for (int i = 0; i < 16; i++){
        int idx = t + i*256;             // 0..4095
        int kk = idx >> 6, n = idx & 63;
        tile[kk*65 + n] = W[(size_t)(k0 + kk)*64 + n];
    }
    __syncthreads();

    // coalesced write: adjacent threads -> adjacent k (bf16, 128B rows)
    __nv_bfloat16* ghi = g_wt + (size_t)(z*2+0)*65536;
    __nv_bfloat16* glo = g_wt + (size_t)(z*2+1)*65536;
    #pragma unroll
    for (int i = 0; i < 16; i++){
        int idx = t + i*256;
        int n = idx >> 6, kk = idx & 63;
        float w = tile[kk*65 + n];
        __nv_bfloat16 h = __float2bfloat16(w);
        float r = w - __bfloat162float(h);
        ghi[(size_t)n*1024 + k0 + kk] = h;
        glo[(size_t)n*1024 + k0 + kk] = __float2bfloat16(r);
    }
}

// =====================================================================
// Kernel 1: HMMA split-bf16 projection (R10 winner: 256 thr, pipelined
// A convert hidden under the tensor phase, one barrier per chunk)
// =====================================================================
#define KCH 64
#define NCHUNK (Cv/KCH)
#define A_HI 0
#define A_LO 36864
#define B_HI 73728
#define B_LO 110592
#define PROJ_SMEM 147456

__device__ __forceinline__ void cvt_split4(float4 a, uint2 &hi, uint2 &lo){
    __nv_bfloat162 h01 = __floats2bfloat162_rn(a.x, a.y);
    __nv_bfloat162 h23 = __floats2bfloat162_rn(a.z, a.w);
    float2 f01 = __bfloat1622float2(h01);
    float2 f23 = __bfloat1622float2(h23);
    __nv_bfloat162 l01 = __floats2bfloat162_rn(a.x - f01.x, a.y - f01.y);
    __nv_bfloat162 l23 = __floats2bfloat162_rn(a.z - f23.x, a.w - f23.y);
    hi.x = *(u32*)&h01; hi.y = *(u32*)&h23;
    lo.x = *(u32*)&l01; lo.y = *(u32*)&l23;
}

__global__ __launch_bounds__(256) void proj_mma(
    const float* __restrict__ qv, const float* __restrict__ kvec,
    const float* __restrict__ vv)
{
    extern __shared__ __align__(128) char smc[];
    const int t   = threadIdx.x;
    const int wid = t >> 5;
    const int l   = t & 31;
    const int z   = blockIdx.y;
    const int m0  = blockIdx.x * 128;
    const float* A = (z==0) ? qv : (z==1) ? kvec : vv;

    const u32 sbase = smem_u32(smc);
    const int wm = wid >> 1;
    const int wn = wid & 1;

    const int arow  = (l & 15);
    const int acol8 = (l >> 4) * 8;
    const int brow  = (l & 7);
    const int bk8   = ((l >> 3) & 1) * 8;

    auto loadB = [&](int it2){
        int slot = it2 & 3; int k0 = it2 * KCH;
        #pragma unroll
        for (int i = 0; i < 4; i++){
            int idx = t + i*256;
            int term = idx >> 9;
            int rem = idx & 511;
            int n = rem >> 3, c = rem & 7;
            cp16(smc + (term ? B_LO : B_HI) + slot*9216 + n*144 + c*16,
                 g_wt + (size_t)(z*2+term)*65536 + n*1024 + k0 + c*8);
        }
    };

    float4 aPre[8];
    auto loadA = [&](int it2){
        int k0 = it2 * KCH;
        #pragma unroll
        for (int i = 0; i < 8; i++){
            int idx = t + i*256; int r = idx >> 4, c4 = idx & 15;
            aPre[i] = *(const float4*)(A + (size_t)(m0 + r)*Cv + k0 + c4*4);
        }
    };

    auto stsA = [&](int buf){
        #pragma unroll
        for (int i = 0; i < 8; i++){
            int idx = t + i*256; int r = idx >> 4, c4 = idx & 15;
            uint2 hi, lo; cvt_split4(aPre[i], hi, lo);
            *(uint2*)(smc + A_HI + buf*18432 + r*144 + c4*8) = hi;
            *(uint2*)(smc + A_LO + buf*18432 + r*144 + c4*8) = lo;
        }
    };

    // prologue: A(0) converted+stored, A(1) in regs, B(0),B(1) in flight
    loadA(0);
    loadB(0); CP_COMMIT();
    loadB(1); CP_COMMIT();
    stsA(0);
    loadA(1);
    __syncthreads();

    float D[2][4][4];
    #pragma unroll
    for (int mt = 0; mt < 2; mt++)
        #pragma unroll
        for (int nc = 0; nc < 4; nc++)
            #pragma unroll
            for (int e = 0; e < 4; e++) D[mt][nc][e] = 0.f;

    #pragma unroll 1
    for (int it = 0; it < NCHUNK; it++){
        if (it < NCHUNK-1) { CP_WAIT1(); } else { CP_WAIT0(); }   // B(it) resident
        const int buf = it & 1;
        const int slot = it & 3;

        if (it + 2 < NCHUNK){ loadB(it + 2); CP_COMMIT(); }

        const u32 aHiB = sbase + A_HI + buf*18432;
        const u32 aLoB = sbase + A_LO + buf*18432;
        const u32 bHiB = sbase + B_HI + slot*9216;
        const u32 bLoB = sbase + B_LO + slot*9216;

        #pragma unroll
        for (int ks = 0; ks < 4; ks++){
            u32 AH[2][4], AL[2][4], BH[4][2], BL[4][2];
            #pragma unroll
            for (int mt = 0; mt < 2; mt++){
                u32 ao = (u32)((wm*32 + mt*16 + arow)*144 + (ks*16 + acol8)*2);
                ldsm_x4(AH[mt][0], AH[mt][1], AH[mt][2], AH[mt][3], aHiB + ao);
                ldsm_x4(AL[mt][0], AL[mt][1], AL[mt][2], AL[mt][3], aLoB + ao);
            }
            #pragma unroll
            for (int nc = 0; nc < 4; nc++){
                u32 bo = (u32)((wn*32 + nc*8 + brow)*144 + (ks*16 + bk8)*2);
                ldsm_x2(BH[nc][0], BH[nc][1], bHiB + bo);
                ldsm_x2(BL[nc][0], BL[nc][1], bLoB + bo);
            }
            #pragma unroll
            for (int mt = 0; mt < 2; mt++)
                #pragma unroll
                for (int nc = 0; nc < 4; nc++){
                    mma16816(D[mt][nc], AH[mt], BH[nc]);
                    mma16816(D[mt][nc], AH[mt], BL[nc]);
                    mma16816(D[mt][nc], AL[mt], BH[nc]);
                }
        }

        // hidden under the tensor phase: convert+store A(it+1), prefetch A(it+2)
        if (it + 1 < NCHUNK){
            stsA((it + 1) & 1);
            if (it + 2 < NCHUNK) loadA(it + 2);
        }
        __syncthreads();
    }

    const float sc = (z == 0) ? 0.125f : 1.0f;
    __nv_bfloat16* ghi = g_abuf + (size_t)(z*2+0)*Mv*HSv;
    __nv_bfloat16* glo = g_abuf + (size_t)(z*2+1)*Mv*HSv;
    #pragma unroll
    for (int mt = 0; mt < 2; mt++){
        int row = m0 + wm*32 + mt*16 + (l >> 2);
        #pragma unroll
        for (int nc = 0; nc < 4; nc++){
            int col = wn*32 + nc*8 + (l & 3)*2;
            u32 h0, l0, h1, l1;
            split_pair(D[mt][nc][0]*sc, D[mt][nc][1]*sc, h0, l0);
            split_pair(D[mt][nc][2]*sc, D[mt][nc][3]*sc, h1, l1);
            *(u32*)(ghi + (size_t)row*HSv + col)     = h0;
            *(u32*)(glo + (size_t)row*HSv + col)     = l0;
            *(u32*)(ghi + (size_t)(row+8)*HSv + col) = h1;
            *(u32*)(glo + (size_t)(row+8)*HSv + col) = l1;
        }
    }
}

// =====================================================================
// Kernel 2: HMMA attention, 256-key chunks + fused last-CTA merge
// =====================================================================
#define AQH 0
#define AQL 18432
#define SUBOFF(s2) (36864 + (s2)*73728)      // KH +0, KL +18432, VH +36864, VL +55296
#define AMSK 184320
#define ATTN_SMEM (184320 + 1024)

__global__ __launch_bounds__(256, 1) void attn_mma(const int* __restrict__ mask,
                                                   float* __restrict__ out)
{
    extern __shared__ __align__(128) char smc[];
    __shared__ int s_old;
    const u32 sbase = smem_u32(smc);
    int* Msk = (int*)(smc + AMSK);           // [2][128]

    // decode (qb, s): cum(qb) = floor((qb+1)^2/4)
    int x = blockIdx.x;
    int qb = (int)(2.f*sqrtf((float)(x+1))) - 1;
    if (qb < 0) qb = 0; if (qb > 15) qb = 15;
    while (qb < 15 && ((qb+2)*(qb+2))/4 <= x) qb++;
    while (qb > 0 && ((qb+1)*(qb+1))/4 > x) qb--;
    const int s = x - ((qb+1)*(qb+1))/4;

    const int b  = blockIdx.y;
    const int t  = threadIdx.x;
    const int w  = t >> 5;
    const int l  = t & 31;
    const int bT = b*Tv;
    const int row0 = qb*QT;
    const int ks0 = s*256;
    const int nsub = (min(256, (qb+1)*128 - ks0)) >> 7;   // 1 or 2

    auto load_arr = [&](int aa, int dst_off, int src_row0){
        const __nv_bfloat16* src = g_abuf + (size_t)aa*Mv*HSv + (size_t)(bT + src_row0)*HSv;
        #pragma unroll
        for (int i = 0; i < 4; i++){
            int idx = t + i*256; int r = idx >> 3, c = idx & 7;
            cp16(smc + dst_off + r*144 + c*16, src + r*64 + c*8);
        }
    };
    load_arr(2, SUBOFF(0) + 0,     ks0);
    load_arr(3, SUBOFF(0) + 18432, ks0);
    load_arr(0, AQH, row0);
    load_arr(1, AQL, row0);
    if (t < 32) cp16(&Msk[t*4], mask + bT + ks0 + t*4);
    CP_COMMIT();
    load_arr(4, SUBOFF(0) + 36864, ks0);
    load_arr(5, SUBOFF(0) + 55296, ks0);
    CP_COMMIT();
    if (nsub == 2){
        load_arr(2, SUBOFF(1) + 0,     ks0 + 128);
        load_arr(3, SUBOFF(1) + 18432, ks0 + 128);
        if (t < 32) cp16(&Msk[128 + t*4], mask + bT + ks0 + 128 + t*4);
    }
    CP_COMMIT();
    if (nsub == 2){
        load_arr(4, SUBOFF(1) + 36864, ks0 + 128);
        load_arr(5, SUBOFF(1) + 55296, ks0 + 128);
    }
    CP_COMMIT();

    const int arow  = (l & 15);
    const int acol8 = (l >> 4) * 8;
    const int brow  = (l & 7);
    const int bk8   = ((l >> 3) & 1) * 8;
    const int vofs  = (l & 15) * 144;

    CP_WAIT3();
    __syncthreads();

    u32 QH4[4][4], QL4[4][4];
    #pragma unroll
    for (int ks = 0; ks < 4; ks++){
        u32 ao = (u32)((w*16 + arow)*144 + (ks*16 + acol8)*2);
        ldsm_x4(QH4[ks][0], QH4[ks][1], QH4[ks][2], QH4[ks][3], sbase + AQH + ao);
        ldsm_x4(QL4[ks][0], QL4[ks][1], QL4[ks][2], QL4[ks][3], sbase + AQL + ao);
    }

    const int g  = l >> 2;
    const int qx = l & 3;
    const int r0g = row0 + w*16 + g;
    const int r1g = r0g + 8;

    float mraw0 = -INFINITY, mraw1 = -INFINITY;
    float mC0 = -1e30f, mC1 = -1e30f;
    float l0 = 0.f, l1 = 0.f;
    float O[8][4];
    #pragma unroll
    for (int nb = 0; nb < 8; nb++)
        #pragma unroll
        for (int e = 0; e < 4; e++) O[nb][e] = 0.f;

    #pragma unroll 1
    for (int sub = 0; sub < nsub; sub++){
        if (sub == 1){ CP_WAIT1(); __syncthreads(); }
        const u32 kbase = sbase + SUBOFF(sub);
        const int msub = sub*128;
        const int ksub = ks0 + sub*128;

        float S[16][4];
        #pragma unroll
        for (int nt = 0; nt < 16; nt++)
            #pragma unroll
            for (int e = 0; e < 4; e++) S[nt][e] = 0.f;

        #pragma unroll
        for (int ks = 0; ks < 4; ks++){
            #pragma unroll
            for (int nt = 0; nt < 16; nt++){
                u32 bo = (u32)((nt*8 + brow)*144 + (ks*16 + bk8)*2);
                u32 BH0, BH1, BL0, BL1;
                ldsm_x2(BH0, BH1, kbase + bo);
                ldsm_x2(BL0, BL1, kbase + 18432 + bo);
                u32 BH[2] = {BH0, BH1}, BL[2] = {BL0, BL1};
                mma16816(S[nt], QH4[ks], BH);
                mma16816(S[nt], QH4[ks], BL);
                mma16816(S[nt], QL4[ks], BH);
            }
        }

        float tm0 = -INFINITY, tm1 = -INFINITY;
        #pragma unroll
        for (int nt = 0; nt < 16; nt++){
            int kb = ksub + nt*8 + qx*2;
            bool va = (kb   <= r0g) && Msk[msub + nt*8 + qx*2];
            bool vb = (kb+1 <= r0g) && Msk[msub + nt*8 + qx*2 + 1];
            bool vc = (kb   <= r1g) && Msk[msub + nt*8 + qx*2];
            bool vd = (kb+1 <= r1g) && Msk[msub + nt*8 + qx*2 + 1];
            S[nt][0] = va ? S[nt][0] : -INFINITY;
            S[nt][1] = vb ? S[nt][1] : -INFINITY;
            S[nt][2] = vc ? S[nt][2] : -INFINITY;
            S[nt][3] = vd ? S[nt][3] : -INFINITY;
            tm0 = fmaxf(tm0, fmaxf(S[nt][0], S[nt][1]));
            tm1 = fmaxf(tm1, fmaxf(S[nt][2], S[nt][3]));
        }
        tm0 = fmaxf(tm0, __shfl_xor_sync(0xFFFFFFFFu, tm0, 1));
        tm0 = fmaxf(tm0, __shfl_xor_sync(0xFFFFFFFFu, tm0, 2));
        tm1 = fmaxf(tm1, __shfl_xor_sync(0xFFFFFFFFu, tm1, 1));
        tm1 = fmaxf(tm1, __shfl_xor_sync(0xFFFFFFFFu, tm1, 2));

        mraw0 = fmaxf(mraw0, tm0);
        mraw1 = fmaxf(mraw1, tm1);
        float mC0n = fmaxf(mraw0, -1e30f);
        float mC1n = fmaxf(mraw1, -1e30f);
        float sc0 = __expf(mC0 - mC0n);
        float sc1 = __expf(mC1 - mC1n);
        mC0 = mC0n; mC1 = mC1n;

        float ps0 = 0.f, ps1 = 0.f;
        #pragma unroll
        for (int nt = 0; nt < 16; nt++){
            S[nt][0] = __expf(S[nt][0] - mC0);
            S[nt][1] = __expf(S[nt][1] - mC0);
            S[nt][2] = __expf(S[nt][2] - mC1);
            S[nt][3] = __expf(S[nt][3] - mC1);
            ps0 += S[nt][0] + S[nt][1];
            ps1 += S[nt][2] + S[nt][3];
        }
        ps0 += __shfl_xor_sync(0xFFFFFFFFu, ps0, 1);
        ps0 += __shfl_xor_sync(0xFFFFFFFFu, ps0, 2);
        ps1 += __shfl_xor_sync(0xFFFFFFFFu, ps1, 1);
        ps1 += __shfl_xor_sync(0xFFFFFFFFu, ps1, 2);
        l0 = l0*sc0 + ps0;
        l1 = l1*sc1 + ps1;

        #pragma unroll
        for (int nb = 0; nb < 8; nb++){
            O[nb][0] *= sc0; O[nb][1] *= sc0;
            O[nb][2] *= sc1; O[nb][3] *= sc1;
        }

        if (sub == 0){ CP_WAIT2(); } else { CP_WAIT0(); }
        __syncthreads();
        const u32 vbase = kbase + 36864;

        #pragma unroll
        for (int ks = 0; ks < 8; ks++){
            u32 Ph[4], Pl[4];
            split_pair(S[2*ks][0],   S[2*ks][1],   Ph[0], Pl[0]);
            split_pair(S[2*ks][2],   S[2*ks][3],   Ph[1], Pl[1]);
            split_pair(S[2*ks+1][0], S[2*ks+1][1], Ph[2], Pl[2]);
            split_pair(S[2*ks+1][2], S[2*ks+1][3], Ph[3], Pl[3]);
            #pragma unroll
            for (int nb = 0; nb < 8; nb++){
                u32 bo = (u32)(ks*16*144 + vofs + nb*16);
                u32 BH0, BH1, BL0, BL1;
                ldsm_x2t(BH0, BH1, vbase + bo);
                ldsm_x2t(BL0, BL1, vbase + 18432 + bo);
                u32 BH[2] = {BH0, BH1}, BL[2] = {BL0, BL1};
                mma16816(O[nb], Ph, BH);
                mma16816(O[nb], Ph, BL);
                mma16816(O[nb], Pl, BH);
            }
        }
    }

    // ---- write unnormalized partials ----
    if (qx == 0){
        g_pm[s*Mv + bT + r0g] = mraw0;  g_pl[s*Mv + bT + r0g] = l0;
        g_pm[s*Mv + bT + r1g] = mraw1;  g_pl[s*Mv + bT + r1g] = l1;
    }
    #pragma unroll
    for (int nb = 0; nb < 8; nb++){
        int col = nb*8 + qx*2;
        *(float2*)(g_pacc + ((size_t)s*Mv + bT + r0g)*HSv + col) = make_float2(O[nb][0], O[nb][1]);
        *(float2*)(g_pacc + ((size_t)s*Mv + bT + r1g)*HSv + col) = make_float2(O[nb][2], O[nb][3]);
    }

    // ---- last CTA for this (b, qb) merges all partials into out ----
    const int ns_total = (qb + 2) >> 1;
    __threadfence();
    __syncthreads();
    if (t == 0) s_old = atomicAdd(&g_cnt[b*16 + qb], 1);
    __syncthreads();
    if (s_old == ns_total - 1){
        __threadfence();
        #pragma unroll 1
        for (int idx = t; idx < 128*16; idx += 256){
            int grow = bT + row0 + (idx >> 4);
            int c4 = idx & 15;
            float M = -INFINITY;
            for (int s2 = 0; s2 < ns_total; s2++)
                M = fmaxf(M, g_pm[s2*Mv + grow]);
            float4 o = make_float4(0.f, 0.f, 0.f, 0.f);
            if (M > -INFINITY){
                float denom = 0.f;
                for (int s2 = 0; s2 < ns_total; s2++){
                    float wgt = __expf(g_pm[s2*Mv + grow] - M);
                    denom += g_pl[s2*Mv + grow] * wgt;
                    float4 a = ((const float4*)g_pacc)[((size_t)s2*Mv + grow)*16 + c4];
                    o.x += a.x*wgt; o.y += a.y*wgt;
                    o.z += a.z*wgt; o.w += a.w*wgt;
                }
                float inv = (denom > 0.f) ? 1.f/denom : 0.f;
                o.x *= inv; o.y *= inv; o.z *= inv; o.w *= inv;
            }
            ((float4*)out)[(size_t)grow*16 + c4] = o;
        }
        __syncthreads();
        if (t == 0) g_cnt[b*16 + qb] = 0;    // reset for next graph replay
    }
}

// =====================================================================
extern "C" void kernel_launch(void* const* d_in, const int* in_sizes, int n_in,
                              void* d_out, int out_size)
{
    const float* q_vec = (const float*)d_in[0];
    const float* k_vec = (const float*)d_in[1];
    const float* v_vec = (const float*)d_in[2];
    const int*   mask  = (const int*)  d_in[3];
    const float* Wq    = (const float*)d_in[4];
    const float* Wk    = (const float*)d_in[5];
    const float* Wv    = (const float*)d_in[6];
    float* out = (float*)d_out;

    cudaFuncSetAttribute(proj_mma,
        cudaFuncAttributeMaxDynamicSharedMemorySize, PROJ_SMEM);
    cudaFuncSetAttribute(attn_mma,
        cudaFuncAttributeMaxDynamicSharedMemorySize, ATTN_SMEM);

    prep_wt<<<48, 256>>>(Wq, Wk, Wv);
    proj_mma<<<dim3(Mv/128, 3), 256, PROJ_SMEM>>>(q_vec, k_vec, v_vec);
    attn_mma<<<dim3(72, Bv), 256, ATTN_SMEM>>>(mask, out);
}

// round 14
// speedup vs baseline: 1.2613x; 1.2153x over previous
#include <cuda_runtime.h>
#include <cuda_bf16.h>
#include <math.h>

#define Bv 8
#define Tv 2048
#define Cv 1024
#define HSv 64
#define Mv (Bv*Tv)
#define QT 128
#define SLOTS 8

typedef unsigned long long u64;
typedef unsigned int u32;

// ---------- cp.async ----------
__device__ __forceinline__ void cp16(void* dst_smem, const void* src){
    unsigned d = (unsigned)__cvta_generic_to_shared(dst_smem);
    asm volatile("cp.async.cg.shared.global [%0], [%1], 16;" :: "r"(d), "l"(src));
}
#define CP_COMMIT() asm volatile("cp.async.commit_group;")
#define CP_WAIT0()  asm volatile("cp.async.wait_group 0;")
#define CP_WAIT1()  asm volatile("cp.async.wait_group 1;")
#define CP_WAIT2()  asm volatile("cp.async.wait_group 2;")
#define CP_WAIT3()  asm volatile("cp.async.wait_group 3;")

// ---------- mma.sync helpers ----------
__device__ __forceinline__ u32 smem_u32(const void* p){
    return (u32)__cvta_generic_to_shared(p);
}
__device__ __forceinline__ void ldsm_x4(u32 &r0,u32 &r1,u32 &r2,u32 &r3, u32 addr){
    asm volatile("ldmatrix.sync.aligned.m8n8.x4.shared.b16 {%0,%1,%2,%3}, [%4];"
        : "=r"(r0),"=r"(r1),"=r"(r2),"=r"(r3) : "r"(addr));
}
__device__ __forceinline__ void ldsm_x2(u32 &r0,u32 &r1, u32 addr){
    asm volatile("ldmatrix.sync.aligned.m8n8.x2.shared.b16 {%0,%1}, [%2];"
        : "=r"(r0),"=r"(r1) : "r"(addr));
}
__device__ __forceinline__ void ldsm_x2t(u32 &r0,u32 &r1, u32 addr){
    asm volatile("ldmatrix.sync.aligned.m8n8.x2.trans.shared.b16 {%0,%1}, [%2];"
        : "=r"(r0),"=r"(r1) : "r"(addr));
}
__device__ __forceinline__ void mma16816(float* d, const u32* a, const u32* b){
    asm volatile("mma.sync.aligned.m16n8k16.row.col.f32.bf16.bf16.f32 "
        "{%0,%1,%2,%3}, {%4,%5,%6,%7}, {%8,%9}, {%0,%1,%2,%3};"
        : "+f"(d[0]),"+f"(d[1]),"+f"(d[2]),"+f"(d[3])
        : "r"(a[0]),"r"(a[1]),"r"(a[2]),"r"(a[3]), "r"(b[0]),"r"(b[1]));
}

__device__ __forceinline__ void split_pair(float x, float y, u32 &h, u32 &lo){
    __nv_bfloat162 hh = __floats2bfloat162_rn(x, y);
    float2 fo = __bfloat1622float2(hh);
    __nv_bfloat162 ll = __floats2bfloat162_rn(x - fo.x, y - fo.y);
    h  = *(u32*)&hh;
    lo = *(u32*)&ll;
}

// ---------- scratch ----------
__device__ __nv_bfloat16 g_abuf[6*(size_t)Mv*HSv];
__device__ float g_pacc[(size_t)SLOTS*Mv*HSv];
__device__ float g_pm[SLOTS*Mv];
__device__ float g_pl[SLOTS*Mv];
__device__ __nv_bfloat16 g_wt[3*2*64*1024];   // [z][hi/lo][n][k]

// =====================================================================
// Kernel 0: transpose + bf16-split weights (R10 version)
// =====================================================================
__global__ __launch_bounds__(256) void prep_wt(
    const float* __restrict__ Wq, const float* __restrict__ Wk,
    const float* __restrict__ Wv)
{
    int id = blockIdx.x*256 + threadIdx.x;
    int z = id >> 16; int rem = id & 65535;
    int n = rem >> 10; int k = rem & 1023;
    const float* W = (z==0) ? Wq : (z==1) ? Wk : Wv;
    float w = W[k*64 + n];
    __nv_bfloat16 h = __float2bfloat16(w);
    float r = w - __bfloat162float(h);
    g_wt[(size_t)(z*2+0)*65536 + n*1024 + k] = h;
    g_wt[(size_t)(z*2+1)*65536 + n*1024 + k] = __float2bfloat16(r);
}

// =====================================================================
// Kernel 1: HMMA split-bf16 projection, KCH=32 / 80KB smem / 2 CTAs/SM.
// 80-byte rows (16B-aligned cp.async dst, conflict-free ldmatrix).
// Pipelined A convert under tensor phase (R10 structure).
// =====================================================================
#define KCH 32
#define NCHUNK (Cv/KCH)     // 32
#define AROW 80
#define BROWB 80
#define A_HI 0              // 2 bufs x 10240
#define A_LO 20480          // 2 bufs x 10240
#define B_HI 40960          // 4 slots x 5120
#define B_LO 61440          // 4 slots x 5120
#define PROJ_SMEM 81920

__device__ __forceinline__ void cvt_split4(float4 a, uint2 &hi, uint2 &lo){
    __nv_bfloat162 h01 = __floats2bfloat162_rn(a.x, a.y);
    __nv_bfloat162 h23 = __floats2bfloat162_rn(a.z, a.w);
    float2 f01 = __bfloat1622float2(h01);
    float2 f23 = __bfloat1622float2(h23);
    __nv_bfloat162 l01 = __floats2bfloat162_rn(a.x - f01.x, a.y - f01.y);
    __nv_bfloat162 l23 = __floats2bfloat162_rn(a.z - f23.x, a.w - f23.y);
    hi.x = *(u32*)&h01; hi.y = *(u32*)&h23;
    lo.x = *(u32*)&l01; lo.y = *(u32*)&l23;
}

__global__ __launch_bounds__(256, 2) void proj_mma(
    const float* __restrict__ qv, const float* __restrict__ kvec,
    const float* __restrict__ vv)
{
    extern __shared__ __align__(128) char smc[];
    const int t   = threadIdx.x;
    const int wid = t >> 5;
    const int l   = t & 31;
    const int z   = blockIdx.y;
    const int m0  = blockIdx.x * 128;
    const float* A = (z==0) ? qv : (z==1) ? kvec : vv;

    const u32 sbase = smem_u32(smc);
    const int wm = wid >> 1;
    const int wn = wid & 1;

    const int arow  = (l & 15);
    const int acol8 = (l >> 4) * 8;
    const int brow  = (l & 7);
    const int bk8   = ((l >> 3) & 1) * 8;

    auto loadB = [&](int it2){
        int slot = it2 & 3; int k0 = it2 * KCH;
        #pragma unroll
        for (int i = 0; i < 2; i++){
            int idx = t + i*256;              // 0..511
            int term = idx >> 8;
            int rem = idx & 255;
            int n = rem >> 2, c = rem & 3;    // 64 rows x 4 chunks of 16B
            cp16(smc + (term ? B_LO : B_HI) + slot*5120 + n*BROWB + c*16,
                 g_wt + (size_t)(z*2+term)*65536 + n*1024 + k0 + c*8);
        }
    };

    float4 aPre[4];
    auto loadA = [&](int it2){
        int k0 = it2 * KCH;
        #pragma unroll
        for (int i = 0; i < 4; i++){
            int idx = t + i*256; int r = idx >> 3, c4 = idx & 7;
            aPre[i] = *(const float4*)(A + (size_t)(m0 + r)*Cv + k0 + c4*4);
        }
    };

    auto stsA = [&](int buf){
        #pragma unroll
        for (int i = 0; i < 4; i++){
            int idx = t + i*256; int r = idx >> 3, c4 = idx & 7;
            uint2 hi, lo; cvt_split4(aPre[i], hi, lo);
            *(uint2*)(smc + A_HI + buf*10240 + r*AROW + c4*8) = hi;
            *(uint2*)(smc + A_LO + buf*10240 + r*AROW + c4*8) = lo;
        }
    };

    // prologue: A(0) converted+stored, A(1) in regs, B(0),B(1) in flight
    loadA(0);
    loadB(0); CP_COMMIT();
    loadB(1); CP_COMMIT();
    stsA(0);
    loadA(1);
    __syncthreads();

    float D[2][4][4];
    #pragma unroll
    for (int mt = 0; mt < 2; mt++)
        #pragma unroll
        for (int nc = 0; nc < 4; nc++)
            #pragma unroll
            for (int e = 0; e < 4; e++) D[mt][nc][e] = 0.f;

    #pragma unroll 1
    for (int it = 0; it < NCHUNK; it++){
        if (it < NCHUNK-1) { CP_WAIT1(); } else { CP_WAIT0(); }   // B(it) resident
        const int buf = it & 1;
        const int slot = it & 3;

        if (it + 2 < NCHUNK){ loadB(it + 2); CP_COMMIT(); }

        const u32 aHiB = sbase + A_HI + buf*10240;
        const u32 aLoB = sbase + A_LO + buf*10240;
        const u32 bHiB = sbase + B_HI + slot*5120;
        const u32 bLoB = sbase + B_LO + slot*5120;

        #pragma unroll
        for (int ks = 0; ks < 2; ks++){
            u32 AH[2][4], AL[2][4], BH[4][2], BL[4][2];
            #pragma unroll
            for (int mt = 0; mt < 2; mt++){
                u32 ao = (u32)((wm*32 + mt*16 + arow)*AROW + (ks*16 + acol8)*2);
                ldsm_x4(AH[mt][0], AH[mt][1], AH[mt][2], AH[mt][3], aHiB + ao);
                ldsm_x4(AL[mt][0], AL[mt][1], AL[mt][2], AL[mt][3], aLoB + ao);
            }
            #pragma unroll
            for (int nc = 0; nc < 4; nc++){
                u32 bo = (u32)((wn*32 + nc*8 + brow)*BROWB + (ks*16 + bk8)*2);
                ldsm_x2(BH[nc][0], BH[nc][1], bHiB + bo);
                ldsm_x2(BL[nc][0], BL[nc][1], bLoB + bo);
            }
            #pragma unroll
            for (int mt = 0; mt < 2; mt++)
                #pragma unroll
                for (int nc = 0; nc < 4; nc++){
                    mma16816(D[mt][nc], AH[mt], BH[nc]);
                    mma16816(D[mt][nc], AH[mt], BL[nc]);
                    mma16816(D[mt][nc], AL[mt], BH[nc]);
                }
        }

        // hidden under the tensor phase: convert+store A(it+1), prefetch A(it+2)
        if (it + 1 < NCHUNK){
            stsA((it + 1) & 1);
            if (it + 2 < NCHUNK) loadA(it + 2);
        }
        __syncthreads();
    }

    const float sc = (z == 0) ? 0.125f : 1.0f;
    __nv_bfloat16* ghi = g_abuf + (size_t)(z*2+0)*Mv*HSv;
    __nv_bfloat16* glo = g_abuf + (size_t)(z*2+1)*Mv*HSv;
    #pragma unroll
    for (int mt = 0; mt < 2; mt++){
        int row = m0 + wm*32 + mt*16 + (l >> 2);
        #pragma unroll
        for (int nc = 0; nc < 4; nc++){
            int col = wn*32 + nc*8 + (l & 3)*2;
            u32 h0, l0, h1, l1;
            split_pair(D[mt][nc][0]*sc, D[mt][nc][1]*sc, h0, l0);
            split_pair(D[mt][nc][2]*sc, D[mt][nc][3]*sc, h1, l1);
            *(u32*)(ghi + (size_t)row*HSv + col)     = h0;
            *(u32*)(glo + (size_t)row*HSv + col)     = l0;
            *(u32*)(ghi + (size_t)(row+8)*HSv + col) = h1;
            *(u32*)(glo + (size_t)(row+8)*HSv + col) = l1;
        }
    }
}

// =====================================================================
// Kernel 2: HMMA attention, 256-key chunks (R9/R10 winner)
// =====================================================================
#define AQH 0
#define AQL 18432
#define SUBOFF(s2) (36864 + (s2)*73728)      // KH +0, KL +18432, VH +36864, VL +55296
#define AMSK 184320
#define ATTN_SMEM (184320 + 1024)

__global__ __launch_bounds__(256, 1) void attn_mma(const int* __restrict__ mask)
{
    extern __shared__ __align__(128) char smc[];
    const u32 sbase = smem_u32(smc);
    int* Msk = (int*)(smc + AMSK);           // [2][128]

    // decode (qb, s): cum(qb) = floor((qb+1)^2/4)
    int x = blockIdx.x;
    int qb = (int)(2.f*sqrtf((float)(x+1))) - 1;
    if (qb < 0) qb = 0; if (qb > 15) qb = 15;
    while (qb < 15 && ((qb+2)*(qb+2))/4 <= x) qb++;
    while (qb > 0 && ((qb+1)*(qb+1))/4 > x) qb--;
    const int s = x - ((qb+1)*(qb+1))/4;

    const int b  = blockIdx.y;
    const int t  = threadIdx.x;
    const int w  = t >> 5;
    const int l  = t & 31;
    const int bT = b*Tv;
    const int row0 = qb*QT;
    const int ks0 = s*256;
    const int nsub = (min(256, (qb+1)*128 - ks0)) >> 7;   // 1 or 2

    auto load_arr = [&](int aa, int dst_off, int src_row0){
        const __nv_bfloat16* src = g_abuf + (size_t)aa*Mv*HSv + (size_t)(bT + src_row0)*HSv;
        #pragma unroll
        for (int i = 0; i < 4; i++){
            int idx = t + i*256; int r = idx >> 3, c = idx & 7;
            cp16(smc + dst_off + r*144 + c*16, src + r*64 + c*8);
        }
    };
    load_arr(2, SUBOFF(0) + 0,     ks0);
    load_arr(3, SUBOFF(0) + 18432, ks0);
    load_arr(0, AQH, row0);
    load_arr(1, AQL, row0);
    if (t < 32) cp16(&Msk[t*4], mask + bT + ks0 + t*4);
    CP_COMMIT();
    load_arr(4, SUBOFF(0) + 36864, ks0);
    load_arr(5, SUBOFF(0) + 55296, ks0);
    CP_COMMIT();
    if (nsub == 2){
        load_arr(2, SUBOFF(1) + 0,     ks0 + 128);
        load_arr(3, SUBOFF(1) + 18432, ks0 + 128);
        if (t < 32) cp16(&Msk[128 + t*4], mask + bT + ks0 + 128 + t*4);
    }
    CP_COMMIT();
    if (nsub == 2){
        load_arr(4, SUBOFF(1) + 36864, ks0 + 128);
        load_arr(5, SUBOFF(1) + 55296, ks0 + 128);
    }
    CP_COMMIT();

    const int arow  = (l & 15);
    const int acol8 = (l >> 4) * 8;
    const int brow  = (l & 7);
    const int bk8   = ((l >> 3) & 1) * 8;
    const int vofs  = (l & 15) * 144;

    CP_WAIT3();
    __syncthreads();

    u32 QH4[4][4], QL4[4][4];
    #pragma unroll
    for (int ks = 0; ks < 4; ks++){
        u32 ao = (u32)((w*16 + arow)*144 + (ks*16 + acol8)*2);
        ldsm_x4(QH4[ks][0], QH4[ks][1], QH4[ks][2], QH4[ks][3], sbase + AQH + ao);
        ldsm_x4(QL4[ks][0], QL4[ks][1], QL4[ks][2], QL4[ks][3], sbase + AQL + ao);
    }

    const int g  = l >> 2;
    const int qx = l & 3;
    const int r0g = row0 + w*16 + g;
    const int r1g = r0g + 8;

    float mraw0 = -INFINITY, mraw1 = -INFINITY;
    float mC0 = -1e30f, mC1 = -1e30f;
    float l0 = 0.f, l1 = 0.f;
    float O[8][4];
    #pragma unroll
    for (int nb = 0; nb < 8; nb++)
        #pragma unroll
        for (int e = 0; e < 4; e++) O[nb][e] = 0.f;

    #pragma unroll 1
    for (int sub = 0; sub < nsub; sub++){
        if (sub == 1){ CP_WAIT1(); __syncthreads(); }
        const u32 kbase = sbase + SUBOFF(sub);
        const int msub = sub*128;
        const int ksub = ks0 + sub*128;

        float S[16][4];
        #pragma unroll
        for (int nt = 0; nt < 16; nt++)
            #pragma unroll
            for (int e = 0; e < 4; e++) S[nt][e] = 0.f;

        #pragma unroll
        for (int ks = 0; ks < 4; ks++){
            #pragma unroll
            for (int nt = 0; nt < 16; nt++){
                u32 bo = (u32)((nt*8 + brow)*144 + (ks*16 + bk8)*2);
                u32 BH0, BH1, BL0, BL1;
                ldsm_x2(BH0, BH1, kbase + bo);
                ldsm_x2(BL0, BL1, kbase + 18432 + bo);
                u32 BH[2] = {BH0, BH1}, BL[2] = {BL0, BL1};
                mma16816(S[nt], QH4[ks], BH);
                mma16816(S[nt], QH4[ks], BL);
                mma16816(S[nt], QL4[ks], BH);
            }
        }

        float tm0 = -INFINITY, tm1 = -INFINITY;
        #pragma unroll
        for (int nt = 0; nt < 16; nt++){
            int kb = ksub + nt*8 + qx*2;
            bool va = (kb   <= r0g) && Msk[msub + nt*8 + qx*2];
            bool vb = (kb+1 <= r0g) && Msk[msub + nt*8 + qx*2 + 1];
            bool vc = (kb   <= r1g) && Msk[msub + nt*8 + qx*2];
            bool vd = (kb+1 <= r1g) && Msk[msub + nt*8 + qx*2 + 1];
            S[nt][0] = va ? S[nt][0] : -INFINITY;
            S[nt][1] = vb ? S[nt][1] : -INFINITY;
            S[nt][2] = vc ? S[nt][2] : -INFINITY;
            S[nt][3] = vd ? S[nt][3] : -INFINITY;
            tm0 = fmaxf(tm0, fmaxf(S[nt][0], S[nt][1]));
            tm1 = fmaxf(tm1, fmaxf(S[nt][2], S[nt][3]));
        }
        tm0 = fmaxf(tm0, __shfl_xor_sync(0xFFFFFFFFu, tm0, 1));
        tm0 = fmaxf(tm0, __shfl_xor_sync(0xFFFFFFFFu, tm0, 2));
        tm1 = fmaxf(tm1, __shfl_xor_sync(0xFFFFFFFFu, tm1, 1));
        tm1 = fmaxf(tm1, __shfl_xor_sync(0xFFFFFFFFu, tm1, 2));

        mraw0 = fmaxf(mraw0, tm0);
        mraw1 = fmaxf(mraw1, tm1);
        float mC0n = fmaxf(mraw0, -1e30f);
        float mC1n = fmaxf(mraw1, -1e30f);
        float sc0 = __expf(mC0 - mC0n);
        float sc1 = __expf(mC1 - mC1n);
        mC0 = mC0n; mC1 = mC1n;

        float ps0 = 0.f, ps1 = 0.f;
        #pragma unroll
        for (int nt = 0; nt < 16; nt++){
            S[nt][0] = __expf(S[nt][0] - mC0);
            S[nt][1] = __expf(S[nt][1] - mC0);
            S[nt][2] = __expf(S[nt][2] - mC1);
            S[nt][3] = __expf(S[nt][3] - mC1);
            ps0 += S[nt][0] + S[nt][1];
            ps1 += S[nt][2] + S[nt][3];
        }
        ps0 += __shfl_xor_sync(0xFFFFFFFFu, ps0, 1);
        ps0 += __shfl_xor_sync(0xFFFFFFFFu, ps0, 2);
        ps1 += __shfl_xor_sync(0xFFFFFFFFu, ps1, 1);
        ps1 += __shfl_xor_sync(0xFFFFFFFFu, ps1, 2);
        l0 = l0*sc0 + ps0;
        l1 = l1*sc1 + ps1;

        #pragma unroll
        for (int nb = 0; nb < 8; nb++){
            O[nb][0] *= sc0; O[nb][1] *= sc0;
            O[nb][2] *= sc1; O[nb][3] *= sc1;
        }

        if (sub == 0){ CP_WAIT2(); } else { CP_WAIT0(); }
        __syncthreads();
        const u32 vbase = kbase + 36864;

        #pragma unroll
        for (int ks = 0; ks < 8; ks++){
            u32 Ph[4], Pl[4];
            split_pair(S[2*ks][0],   S[2*ks][1],   Ph[0], Pl[0]);
            split_pair(S[2*ks][2],   S[2*ks][3],   Ph[1], Pl[1]);
            split_pair(S[2*ks+1][0], S[2*ks+1][1], Ph[2], Pl[2]);
            split_pair(S[2*ks+1][2], S[2*ks+1][3], Ph[3], Pl[3]);
            #pragma unroll
            for (int nb = 0; nb < 8; nb++){
                u32 bo = (u32)(ks*16*144 + vofs + nb*16);
                u32 BH0, BH1, BL0, BL1;
                ldsm_x2t(BH0, BH1, vbase + bo);
                ldsm_x2t(BL0, BL1, vbase + 18432 + bo);
                u32 BH[2] = {BH0, BH1}, BL[2] = {BL0, BL1};
                mma16816(O[nb], Ph, BH);
                mma16816(O[nb], Ph, BL);
                mma16816(O[nb], Pl, BH);
            }
        }
    }

    if (qx == 0){
        g_pm[s*Mv + bT + r0g] = mraw0;  g_pl[s*Mv + bT + r0g] = l0;
        g_pm[s*Mv + bT + r1g] = mraw1;  g_pl[s*Mv + bT + r1g] = l1;
    }
    #pragma unroll
    for (int nb = 0; nb < 8; nb++){
        int col = nb*8 + qx*2;
        *(float2*)(g_pacc + ((size_t)s*Mv + bT + r0g)*HSv + col) = make_float2(O[nb][0], O[nb][1]);
        *(float2*)(g_pacc + ((size_t)s*Mv + bT + r1g)*HSv + col) = make_float2(O[nb][2], O[nb][3]);
    }
}

// =====================================================================
// Kernel 3: merge — fully unrolled predicated loads (R10 winner)
// =====================================================================
__global__ __launch_bounds__(256) void merge_kernel(float* __restrict__ out)
{
    int gid = blockIdx.x * blockDim.x + threadIdx.x;
    int row = gid >> 4, c4 = gid & 15;
    const int qb = (row & (Tv-1)) >> 7;
    const int ns = (qb + 2) >> 1;        // ceil((qb+1)/2), 1..8

    float pm[8], pl[8];
    float4 ac[8];
    #pragma unroll
    for (int s2 = 0; s2 < 8; s2++){
        if (s2 < ns){
            pm[s2] = g_pm[s2*Mv + row];
            pl[s2] = g_pl[s2*Mv + row];
            ac[s2] = ((const float4*)g_pacc)[((size_t)s2*Mv + row)*16 + c4];
        } else {
            pm[s2] = -INFINITY; pl[s2] = 0.f;
            ac[s2] = make_float4(0.f,0.f,0.f,0.f);
        }
    }

    float M = pm[0];
    #pragma unroll
    for (int s2 = 1; s2 < 8; s2++) M = fmaxf(M, pm[s2]);

    float4 o = make_float4(0.f, 0.f, 0.f, 0.f);
    if (M > -INFINITY){
        float denom = 0.f;
        #pragma unroll
        for (int s2 = 0; s2 < 8; s2++){
            float w = __expf(pm[s2] - M);       // 0 for inactive slots
            denom += pl[s2] * w;
            o.x += ac[s2].x*w; o.y += ac[s2].y*w;
            o.z += ac[s2].z*w; o.w += ac[s2].w*w;
        }
        float inv = (denom > 0.f) ? 1.f/denom : 0.f;
        o.x *= inv; o.y *= inv; o.z *= inv; o.w *= inv;
    }
    ((float4*)out)[gid] = o;
}

// =====================================================================
extern "C" void kernel_launch(void* const* d_in, const int* in_sizes, int n_in,
                              void* d_out, int out_size)
{
    const float* q_vec = (const float*)d_in[0];
    const float* k_vec = (const float*)d_in[1];
    const float* v_vec = (const float*)d_in[2];
    const int*   mask  = (const int*)  d_in[3];
    const float* Wq    = (const float*)d_in[4];
    const float* Wk    = (const float*)d_in[5];
    const float* Wv    = (const float*)d_in[6];
    float* out = (float*)d_out;

    cudaFuncSetAttribute(proj_mma,
        cudaFuncAttributeMaxDynamicSharedMemorySize, PROJ_SMEM);
    cudaFuncSetAttribute(attn_mma,
        cudaFuncAttributeMaxDynamicSharedMemorySize, ATTN_SMEM);

    prep_wt<<<768, 256>>>(Wq, Wk, Wv);
    proj_mma<<<dim3(Mv/128, 3), 256, PROJ_SMEM>>>(q_vec, k_vec, v_vec);
    attn_mma<<<dim3(72, Bv), 256, ATTN_SMEM>>>(mask);
    merge_kernel<<<(Mv*16)/256, 256>>>(out);
}